// round 7
// baseline (speedup 1.0000x reference)
#include <cuda_runtime.h>
#include <cstdint>

#define N_NODES 100000
#define N_EDGES 300000
#define HID 32

// Scratch (device globals; no allocation allowed)
__device__ float g_agg1[N_NODES * HID];   // layer1 edge-sum accumulator (memset to 0)
__device__ float g_uvw[N_NODES * 96];     // interleaved per-node rows: [u(32) | v(32) | w(32)]
__device__ float g_agg2[N_NODES * HID];   // layer2 accumulator (init h1@root2+bias2 by k3)

__device__ __forceinline__ void red_add_v4(float* addr, float a, float b, float c, float d) {
    asm volatile("red.global.add.v4.f32 [%0], {%1,%2,%3,%4};"
                 :: "l"(addr), "f"(a), "f"(b), "f"(c), "f"(d) : "memory");
}

// Packed fp32x2 FMA (Blackwell FFMA2; bit-exact fp32, 2x MAC per issue slot)
__device__ __forceinline__ uint64_t ffma2(uint64_t a, uint64_t b, uint64_t c) {
    uint64_t d;
    asm("fma.rn.f32x2 %0, %1, %2, %3;" : "=l"(d) : "l"(a), "l"(b), "l"(c));
    return d;
}
__device__ __forceinline__ uint64_t pack2(float x, float y) {
    uint64_t d; asm("mov.b64 %0, {%1, %2};" : "=l"(d) : "f"(x), "f"(y)); return d;
}
__device__ __forceinline__ float2 unpack2(uint64_t v) {
    float2 r; asm("mov.b64 {%0, %1}, %2;" : "=f"(r.x), "=f"(r.y) : "l"(v)); return r;
}
union F4U2 { float4 f4; uint64_t u[2]; };

// ---------------------------------------------------------------------------
// K2: layer-1 edge messages. 2 edges per thread (even/odd pair), 4 channels.
// ---------------------------------------------------------------------------
__global__ void k2_edges1(const int* __restrict__ ei,
                          const float* __restrict__ ea,
                          const float* __restrict__ nn1_w,
                          const float* __restrict__ nn1_b,
                          const float* __restrict__ x) {
    int t = blockIdx.x * blockDim.x + threadIdx.x;
    if (t >= N_EDGES * 4) return;
    int e = (t >> 3) * 2;                 // even edge of the pair
    int q = (t & 7) * 4;                  // channel base 0..28
    int2   ss  = *reinterpret_cast<const int2*>(&ei[e]);
    int2   dd  = *reinterpret_cast<const int2*>(&ei[N_EDGES + e]);
    float4 eav = *reinterpret_cast<const float4*>(&ea[2 * e]);
    float2 xa  = *reinterpret_cast<const float2*>(&x[ss.x * 2]);
    float2 xb  = *reinterpret_cast<const float2*>(&x[ss.y * 2]);

    float m0[4], m1[4];
#pragma unroll
    for (int c = 0; c < 4; c++) {
        int ch = q + c, ch2 = ch + HID;
        float wA0 = nn1_w[2 * ch + 0],  wA1 = nn1_w[2 * ch + 1],  bA = nn1_b[ch];
        float wB0 = nn1_w[2 * ch2 + 0], wB1 = nn1_w[2 * ch2 + 1], bB = nn1_b[ch2];
        float w0a = fmaf(wA0, eav.x, fmaf(wA1, eav.y, bA));
        float w1a = fmaf(wB0, eav.x, fmaf(wB1, eav.y, bB));
        m0[c] = fmaf(xa.x, w0a, xa.y * w1a);
        float w0b = fmaf(wA0, eav.z, fmaf(wA1, eav.w, bA));
        float w1b = fmaf(wB0, eav.z, fmaf(wB1, eav.w, bB));
        m1[c] = fmaf(xb.x, w0b, xb.y * w1b);
    }
    red_add_v4(&g_agg1[dd.x * HID + q], m0[0], m0[1], m0[2], m0[3]);
    red_add_v4(&g_agg1[dd.y * HID + q], m1[0], m1[1], m1[2], m1[3]);
}

// ---------------------------------------------------------------------------
// K3: per-node precompute for layer 2 (k1 folded in). FFMA2 version.
//   h1 = relu(agg1_edges + x@root1 + bias1)
//   uvw row = [h1@A | h1@B | h1@C]; agg2 = h1@root2 + bias2
// sH stored TRANSPOSED [i][node] (pad 36) so the per-step h for a warp's 4
// nodes is one broadcast LDS.128; node-pairs packed into f32x2 accumulators.
// 64 nodes per block = 2 tiles of 32; weights staged once per block.
// ---------------------------------------------------------------------------
__global__ void k3_node2(const float* __restrict__ x,
                         const float* __restrict__ root1,
                         const float* __restrict__ bias1,
                         const float* __restrict__ nn2_w,
                         const float* __restrict__ nn2_b,
                         const float* __restrict__ root2,
                         const float* __restrict__ bias2) {
    __shared__ float sA[1024], sB[1024], sC[1024], sR[1024];
    __shared__ float sH[HID * 36];     // transposed: sH[i*36 + local_node]
    __shared__ float sR1[64], sB1[32];
    int tid = threadIdx.x;
    for (int k = tid; k < 1024; k += 256) {
        sA[k] = nn2_w[2 * k + 0];
        sB[k] = nn2_w[2 * k + 1];
        sC[k] = nn2_b[k];
        sR[k] = root2[k];
    }
    if (tid < 64) sR1[tid] = root1[tid];
    if (tid < 32) sB1[tid] = bias1[tid];

    int warp = tid >> 5, o = tid & 31;
    int nb = warp * 4;

#pragma unroll
    for (int tile = 0; tile < 2; tile++) {
        int nodeBase = blockIdx.x * 64 + tile * 32;
        __syncthreads();   // weights ready (iter 0) / previous tile compute done
        for (int k = tid; k < 32 * HID; k += 256) {
            int nl = k >> 5, oo = k & 31;
            int n = nodeBase + nl;
            float val = 0.0f;
            if (n < N_NODES) {
                float2 xv = *reinterpret_cast<const float2*>(&x[n * 2]);
                float root = fmaf(xv.x, sR1[oo], fmaf(xv.y, sR1[HID + oo], sB1[oo]));
                val = fmaxf(g_agg1[n * HID + oo] + root, 0.0f);
            }
            sH[oo * 36 + nl] = val;   // transposed store (4-way conflict, staging only)
        }
        __syncthreads();

        uint64_t u01 = 0, u23 = 0, v01 = 0, v23 = 0, w01 = 0, w23 = 0, r01 = 0, r23 = 0;
#pragma unroll
        for (int i = 0; i < HID; i++) {
            F4U2 h; h.f4 = *reinterpret_cast<const float4*>(&sH[i * 36 + nb]); // broadcast LDS.128
            uint64_t wa2 = pack2(sA[i * HID + o], sA[i * HID + o]);
            uint64_t wb2 = pack2(sB[i * HID + o], sB[i * HID + o]);
            uint64_t wc2 = pack2(sC[i * HID + o], sC[i * HID + o]);
            uint64_t wr2 = pack2(sR[i * HID + o], sR[i * HID + o]);
            u01 = ffma2(h.u[0], wa2, u01);  u23 = ffma2(h.u[1], wa2, u23);
            v01 = ffma2(h.u[0], wb2, v01);  v23 = ffma2(h.u[1], wb2, v23);
            w01 = ffma2(h.u[0], wc2, w01);  w23 = ffma2(h.u[1], wc2, w23);
            r01 = ffma2(h.u[0], wr2, r01);  r23 = ffma2(h.u[1], wr2, r23);
        }
        float b2 = bias2[o];
        float2 u0 = unpack2(u01), u1 = unpack2(u23);
        float2 v0 = unpack2(v01), v1 = unpack2(v23);
        float2 w0 = unpack2(w01), w1 = unpack2(w23);
        float2 r0 = unpack2(r01), r1 = unpack2(r23);
        float uu[4] = {u0.x, u0.y, u1.x, u1.y};
        float vv[4] = {v0.x, v0.y, v1.x, v1.y};
        float ww[4] = {w0.x, w0.y, w1.x, w1.y};
        float rr[4] = {r0.x, r0.y, r1.x, r1.y};
#pragma unroll
        for (int j = 0; j < 4; j++) {
            int n = nodeBase + nb + j;
            if (n < N_NODES) {
                g_uvw[n * 96 + o]      = uu[j];
                g_uvw[n * 96 + 32 + o] = vv[j];
                g_uvw[n * 96 + 64 + o] = ww[j];
                g_agg2[n * HID + o]    = rr[j] + b2;
            }
        }
    }
}

// ---------------------------------------------------------------------------
// K4: layer-2 edge messages. 2 edges per thread, 4 channels (float4) each.
// ---------------------------------------------------------------------------
__global__ void k4_edges2(const int* __restrict__ ei,
                          const float* __restrict__ ea) {
    int t = blockIdx.x * blockDim.x + threadIdx.x;
    if (t >= N_EDGES * 4) return;
    int e = (t >> 3) * 2;
    int q = (t & 7) * 4;
    int2   ss  = *reinterpret_cast<const int2*>(&ei[e]);
    int2   dd  = *reinterpret_cast<const int2*>(&ei[N_EDGES + e]);
    float4 eav = *reinterpret_cast<const float4*>(&ea[2 * e]);

    const float* ba = g_uvw + ss.x * 96;
    const float* bb = g_uvw + ss.y * 96;
    float4 u0 = *reinterpret_cast<const float4*>(ba + q);
    float4 v0 = *reinterpret_cast<const float4*>(ba + 32 + q);
    float4 w0 = *reinterpret_cast<const float4*>(ba + 64 + q);
    float4 u1 = *reinterpret_cast<const float4*>(bb + q);
    float4 v1 = *reinterpret_cast<const float4*>(bb + 32 + q);
    float4 w1 = *reinterpret_cast<const float4*>(bb + 64 + q);

    float a0 = fmaf(eav.x, u0.x, fmaf(eav.y, v0.x, w0.x));
    float a1 = fmaf(eav.x, u0.y, fmaf(eav.y, v0.y, w0.y));
    float a2 = fmaf(eav.x, u0.z, fmaf(eav.y, v0.z, w0.z));
    float a3 = fmaf(eav.x, u0.w, fmaf(eav.y, v0.w, w0.w));
    red_add_v4(&g_agg2[dd.x * HID + q], a0, a1, a2, a3);

    float b0 = fmaf(eav.z, u1.x, fmaf(eav.w, v1.x, w1.x));
    float b1 = fmaf(eav.z, u1.y, fmaf(eav.w, v1.y, w1.y));
    float b2 = fmaf(eav.z, u1.z, fmaf(eav.w, v1.z, w1.z));
    float b3 = fmaf(eav.z, u1.w, fmaf(eav.w, v1.w, w1.w));
    red_add_v4(&g_agg2[dd.y * HID + q], b0, b1, b2, b3);
}

// ---------------------------------------------------------------------------
// K5: epilogue. 2 threads per node (16 output channels each), FFMA2 inner
// product, pair combined with one shfl_xor. 128 threads = 64 nodes/block;
// 200k threads total -> ~2x warp residency vs thread-per-node.
// ---------------------------------------------------------------------------
#define K5_NODES 64
#define K5_THREADS 128
__global__ void k5_final(const float* __restrict__ fc1_w,
                         const float* __restrict__ fc1_b,
                         const float* __restrict__ fc2_w,
                         const float* __restrict__ fc2_b,
                         float* __restrict__ out) {
    __shared__ float sW[HID * HID];        // fc1_w, row-major (as-is)
    __shared__ float sb[HID];
    __shared__ float sf2[HID];
    __shared__ float sH[K5_NODES * 36];    // padded h2 rows
    int tid = threadIdx.x;
    for (int k = tid; k < HID * HID; k += K5_THREADS) sW[k] = fc1_w[k];   // coalesced
    if (tid < HID) { sb[tid] = fc1_b[tid]; sf2[tid] = fc2_w[tid]; }

    int base = blockIdx.x * K5_NODES;
    for (int k = tid; k < K5_NODES * HID; k += K5_THREADS) {
        int nl = k >> 5, i = k & 31;
        int n = base + nl;
        float v = 0.0f;
        if (n < N_NODES) v = fmaxf(g_agg2[n * HID + i], 0.0f);     // coalesced
        sH[nl * 36 + i] = v;                                        // conflict-free
    }
    __syncthreads();

    int nl = tid >> 1, half = tid & 1;
    // This thread's node: 32 h values as 8 float4 -> 16 packed f32x2.
    F4U2 h4[8];
    const float4* hp = reinterpret_cast<const float4*>(&sH[nl * 36]);
#pragma unroll
    for (int i = 0; i < 8; i++) h4[i].f4 = hp[i];

    const float4* w4 = reinterpret_cast<const float4*>(sW);
    float total = 0.0f;
#pragma unroll 4
    for (int o = 0; o < 16; o++) {
        int oc = half * 16 + o;
        uint64_t a01 = pack2(sb[oc], 0.0f), a23 = 0;
#pragma unroll
        for (int i = 0; i < 8; i++) {
            F4U2 w; w.f4 = w4[oc * 8 + i];     // 2-address broadcast LDS.128
            a01 = ffma2(h4[i].u[0], w.u[0], a01);
            a23 = ffma2(h4[i].u[1], w.u[1], a23);
        }
        float2 a = unpack2(a01), b = unpack2(a23);
        float acc = (a.x + a.y) + (b.x + b.y);
        total = fmaf(fmaxf(acc, 0.0f), sf2[oc], total);
    }
    total += __shfl_xor_sync(0xFFFFFFFFu, total, 1);
    int n = base + nl;
    if (half == 0 && n < N_NODES) out[n] = total + fc2_b[0];
}

// ---------------------------------------------------------------------------
extern "C" void kernel_launch(void* const* d_in, const int* in_sizes, int n_in,
                              void* d_out, int out_size) {
    const float* x       = (const float*)d_in[0];
    const int*   ei      = (const int*)  d_in[1];
    const float* ea      = (const float*)d_in[2];
    const float* nn1_w   = (const float*)d_in[3];
    const float* nn1_b   = (const float*)d_in[4];
    const float* root1   = (const float*)d_in[5];
    const float* bias1   = (const float*)d_in[6];
    const float* nn2_w   = (const float*)d_in[7];
    const float* nn2_b   = (const float*)d_in[8];
    const float* root2   = (const float*)d_in[9];
    const float* bias2   = (const float*)d_in[10];
    const float* fc1_w   = (const float*)d_in[11];
    const float* fc1_b   = (const float*)d_in[12];
    const float* fc2_w   = (const float*)d_in[13];
    const float* fc2_b   = (const float*)d_in[14];
    float* out = (float*)d_out;

    const int tpb = 256;
    int gridEdge = (N_EDGES * 4 + tpb - 1) / tpb;         // 4688
    int gridK3   = (N_NODES + 63) / 64;                   // 1563
    int gridK5   = (N_NODES + K5_NODES - 1) / K5_NODES;   // 1563

    void* agg1_ptr = nullptr;
    cudaGetSymbolAddress(&agg1_ptr, g_agg1);
    cudaMemsetAsync(agg1_ptr, 0, sizeof(float) * N_NODES * HID, 0);

    k2_edges1<<<gridEdge, tpb>>>(ei, ea, nn1_w, nn1_b, x);
    k3_node2<<<gridK3, tpb>>>(x, root1, bias1, nn2_w, nn2_b, root2, bias2);
    k4_edges2<<<gridEdge, tpb>>>(ei, ea);
    k5_final<<<gridK5, K5_THREADS>>>(fc1_w, fc1_b, fc2_w, fc2_b, out);
}

// round 8
// speedup vs baseline: 1.2698x; 1.2698x over previous
#include <cuda_runtime.h>
#include <cstdint>

#define N_NODES 100000
#define N_EDGES 300000
#define HID 32

// Scratch (device globals; no allocation allowed). 16B-aligned for v4 access.
__device__ __align__(16) float g_agg1[N_NODES * HID];  // layer1 edge-sum accumulator (memset 0)
__device__ __align__(16) float g_uvw[N_NODES * 96];    // per-node rows: [u(32) | v(32) | w(32)]
__device__ __align__(16) float g_agg2[N_NODES * HID];  // layer2 accumulator

__device__ __forceinline__ void red_add_v4(float* addr, float a, float b, float c, float d) {
    asm volatile("red.global.add.v4.f32 [%0], {%1,%2,%3,%4};"
                 :: "l"(addr), "f"(a), "f"(b), "f"(c), "f"(d) : "memory");
}

__device__ __forceinline__ uint32_t to_tf32(float f) {
    uint32_t r; asm("cvt.rna.tf32.f32 %0, %1;" : "=r"(r) : "f"(f)); return r;
}

__device__ __forceinline__ void mma_tf32_16n8k8(float c[4],
                                                uint32_t a0, uint32_t a1, uint32_t a2, uint32_t a3,
                                                uint32_t b0, uint32_t b1) {
    asm volatile(
        "mma.sync.aligned.m16n8k8.row.col.f32.tf32.tf32.f32 "
        "{%0,%1,%2,%3}, {%4,%5,%6,%7}, {%8,%9}, {%0,%1,%2,%3};"
        : "+f"(c[0]), "+f"(c[1]), "+f"(c[2]), "+f"(c[3])
        : "r"(a0), "r"(a1), "r"(a2), "r"(a3), "r"(b0), "r"(b1));
}

// ---------------------------------------------------------------------------
// K2: layer-1 edge messages. 2 edges per thread (even/odd pair), 4 channels.
// ---------------------------------------------------------------------------
__global__ void k2_edges1(const int* __restrict__ ei,
                          const float* __restrict__ ea,
                          const float* __restrict__ nn1_w,
                          const float* __restrict__ nn1_b,
                          const float* __restrict__ x) {
    int t = blockIdx.x * blockDim.x + threadIdx.x;
    if (t >= N_EDGES * 4) return;
    int e = (t >> 3) * 2;
    int q = (t & 7) * 4;
    int2   ss  = *reinterpret_cast<const int2*>(&ei[e]);
    int2   dd  = *reinterpret_cast<const int2*>(&ei[N_EDGES + e]);
    float4 eav = *reinterpret_cast<const float4*>(&ea[2 * e]);
    float2 xa  = *reinterpret_cast<const float2*>(&x[ss.x * 2]);
    float2 xb  = *reinterpret_cast<const float2*>(&x[ss.y * 2]);

    float m0[4], m1[4];
#pragma unroll
    for (int c = 0; c < 4; c++) {
        int ch = q + c, ch2 = ch + HID;
        float wA0 = nn1_w[2 * ch + 0],  wA1 = nn1_w[2 * ch + 1],  bA = nn1_b[ch];
        float wB0 = nn1_w[2 * ch2 + 0], wB1 = nn1_w[2 * ch2 + 1], bB = nn1_b[ch2];
        float w0a = fmaf(wA0, eav.x, fmaf(wA1, eav.y, bA));
        float w1a = fmaf(wB0, eav.x, fmaf(wB1, eav.y, bB));
        m0[c] = fmaf(xa.x, w0a, xa.y * w1a);
        float w0b = fmaf(wA0, eav.z, fmaf(wA1, eav.w, bA));
        float w1b = fmaf(wB0, eav.z, fmaf(wB1, eav.w, bB));
        m1[c] = fmaf(xb.x, w0b, xb.y * w1b);
    }
    red_add_v4(&g_agg1[dd.x * HID + q], m0[0], m0[1], m0[2], m0[3]);
    red_add_v4(&g_agg1[dd.y * HID + q], m1[0], m1[1], m1[2], m1[3]);
}

// ---------------------------------------------------------------------------
// K3: tensor-core (tf32 mma.sync) per-node precompute for layer 2.
//   H[128x32] = relu(agg1 + x@root1 + bias1)  (per block, tf32 in smem)
//   Wcat[32x128] = [A | B | C | root2]        (tf32 in smem)
//   D = H @ Wcat -> chans 0-95 -> g_uvw ; chans 96-127 (+bias2) -> g_agg2
// 256 threads = 8 warps; warp w owns m-tile of 16 nodes; 16 n-tiles x 4 k-chunks.
// sH pad 36 (bank 4m+k), sW pad 136 (bank 8k+n): fragment loads conflict-free.
// ---------------------------------------------------------------------------
__global__ void k3_node2(const float* __restrict__ x,
                         const float* __restrict__ root1,
                         const float* __restrict__ bias1,
                         const float* __restrict__ nn2_w,
                         const float* __restrict__ nn2_b,
                         const float* __restrict__ root2,
                         const float* __restrict__ bias2) {
    __shared__ uint32_t sH[128 * 36];   // tf32 H: sH[m*36 + k]
    __shared__ uint32_t sW[32 * 136];   // tf32 Wcat: sW[k*136 + chan]
    __shared__ float sB2[32], sR1[64], sB1[32];
    int tid = threadIdx.x;
    if (tid < 64) sR1[tid] = root1[tid];
    if (tid < 32) { sB1[tid] = bias1[tid]; sB2[tid] = bias2[tid]; }
    __syncthreads();

    // Stage Wcat (tf32)
    for (int idx = tid; idx < 32 * 128; idx += 256) {
        int k = idx >> 7, c = idx & 127;
        float w;
        if (c < 32)       w = nn2_w[(k * 32 + c) * 2 + 0];
        else if (c < 64)  w = nn2_w[(k * 32 + c - 32) * 2 + 1];
        else if (c < 96)  w = nn2_b[k * 32 + c - 64];
        else              w = root2[k * 32 + c - 96];
        sW[k * 136 + c] = to_tf32(w);
    }

    // Stage H (relu(agg1 + x@root1 + bias1)) as tf32
    int blockBase = blockIdx.x * 128;
    for (int idx = tid; idx < 128 * 32; idx += 256) {
        int m = idx >> 5, kk = idx & 31;
        int n = blockBase + m;
        float val = 0.0f;
        if (n < N_NODES) {
            float2 xv = *reinterpret_cast<const float2*>(&x[n * 2]);
            float root = fmaf(xv.x, sR1[kk], fmaf(xv.y, sR1[HID + kk], sB1[kk]));
            val = fmaxf(g_agg1[n * HID + kk] + root, 0.0f);
        }
        sH[m * 36 + kk] = to_tf32(val);
    }
    __syncthreads();

    int warp = tid >> 5, lane = tid & 31;
    int gid = lane >> 2, tig = lane & 3;
    int mloc = warp * 16;

    // A fragments (fixed for this warp): 4 k-chunks x 4 regs
    uint32_t a[4][4];
#pragma unroll
    for (int kc = 0; kc < 4; kc++) {
        int k0 = kc * 8 + tig;
        a[kc][0] = sH[(mloc + gid) * 36 + k0];
        a[kc][1] = sH[(mloc + gid + 8) * 36 + k0];
        a[kc][2] = sH[(mloc + gid) * 36 + k0 + 4];
        a[kc][3] = sH[(mloc + gid + 8) * 36 + k0 + 4];
    }

    int node0 = blockBase + mloc + gid;
    int node1 = node0 + 8;
#pragma unroll
    for (int nt = 0; nt < 16; nt++) {
        float c[4] = {0.0f, 0.0f, 0.0f, 0.0f};
#pragma unroll
        for (int kc = 0; kc < 4; kc++) {
            uint32_t b0 = sW[(kc * 8 + tig) * 136 + nt * 8 + gid];
            uint32_t b1 = sW[(kc * 8 + tig + 4) * 136 + nt * 8 + gid];
            mma_tf32_16n8k8(c, a[kc][0], a[kc][1], a[kc][2], a[kc][3], b0, b1);
        }
        int chan = nt * 8 + tig * 2;
        if (nt < 12) {   // chans 0..95 -> g_uvw
            if (node0 < N_NODES)
                *reinterpret_cast<float2*>(&g_uvw[node0 * 96 + chan]) = make_float2(c[0], c[1]);
            if (node1 < N_NODES)
                *reinterpret_cast<float2*>(&g_uvw[node1 * 96 + chan]) = make_float2(c[2], c[3]);
        } else {         // chans 96..127 -> g_agg2 (+bias2)
            int cb = chan - 96;
            float b0f = sB2[cb], b1f = sB2[cb + 1];
            if (node0 < N_NODES)
                *reinterpret_cast<float2*>(&g_agg2[node0 * HID + cb]) = make_float2(c[0] + b0f, c[1] + b1f);
            if (node1 < N_NODES)
                *reinterpret_cast<float2*>(&g_agg2[node1 * HID + cb]) = make_float2(c[2] + b0f, c[3] + b1f);
        }
    }
}

// ---------------------------------------------------------------------------
// K4: layer-2 edge messages. 2 edges per thread, 4 channels (float4) each.
// ---------------------------------------------------------------------------
__global__ void k4_edges2(const int* __restrict__ ei,
                          const float* __restrict__ ea) {
    int t = blockIdx.x * blockDim.x + threadIdx.x;
    if (t >= N_EDGES * 4) return;
    int e = (t >> 3) * 2;
    int q = (t & 7) * 4;
    int2   ss  = *reinterpret_cast<const int2*>(&ei[e]);
    int2   dd  = *reinterpret_cast<const int2*>(&ei[N_EDGES + e]);
    float4 eav = *reinterpret_cast<const float4*>(&ea[2 * e]);

    const float* ba = g_uvw + ss.x * 96;
    const float* bb = g_uvw + ss.y * 96;
    float4 u0 = *reinterpret_cast<const float4*>(ba + q);
    float4 v0 = *reinterpret_cast<const float4*>(ba + 32 + q);
    float4 w0 = *reinterpret_cast<const float4*>(ba + 64 + q);
    float4 u1 = *reinterpret_cast<const float4*>(bb + q);
    float4 v1 = *reinterpret_cast<const float4*>(bb + 32 + q);
    float4 w1 = *reinterpret_cast<const float4*>(bb + 64 + q);

    float a0 = fmaf(eav.x, u0.x, fmaf(eav.y, v0.x, w0.x));
    float a1 = fmaf(eav.x, u0.y, fmaf(eav.y, v0.y, w0.y));
    float a2 = fmaf(eav.x, u0.z, fmaf(eav.y, v0.z, w0.z));
    float a3 = fmaf(eav.x, u0.w, fmaf(eav.y, v0.w, w0.w));
    red_add_v4(&g_agg2[dd.x * HID + q], a0, a1, a2, a3);

    float b0 = fmaf(eav.z, u1.x, fmaf(eav.w, v1.x, w1.x));
    float b1 = fmaf(eav.z, u1.y, fmaf(eav.w, v1.y, w1.y));
    float b2 = fmaf(eav.z, u1.z, fmaf(eav.w, v1.z, w1.z));
    float b3 = fmaf(eav.z, u1.w, fmaf(eav.w, v1.w, w1.w));
    red_add_v4(&g_agg2[dd.y * HID + q], b0, b1, b2, b3);
}

// ---------------------------------------------------------------------------
// K5: epilogue, thread-per-node (proven R5 config: 256 nodes / 256 threads).
// ---------------------------------------------------------------------------
#define K5_NODES 256
__global__ void k5_final(const float* __restrict__ fc1_w,
                         const float* __restrict__ fc1_b,
                         const float* __restrict__ fc2_w,
                         const float* __restrict__ fc2_b,
                         float* __restrict__ out) {
    __shared__ float sW[HID * HID];        // fc1_w, row-major (as-is)
    __shared__ float sb[HID];
    __shared__ float sf2[HID];
    __shared__ float sH[K5_NODES * 36];    // padded h2 rows
    int tid = threadIdx.x;
    for (int k = tid; k < HID * HID; k += 256) sW[k] = fc1_w[k];   // coalesced
    if (tid < HID) { sb[tid] = fc1_b[tid]; sf2[tid] = fc2_w[tid]; }

    int base = blockIdx.x * K5_NODES;
    for (int k = tid; k < K5_NODES * HID; k += 256) {
        int nl = k >> 5, i = k & 31;
        int n = base + nl;
        float v = 0.0f;
        if (n < N_NODES) v = fmaxf(g_agg2[n * HID + i], 0.0f);     // coalesced
        sH[nl * 36 + i] = v;                                        // conflict-free
    }
    __syncthreads();

    float4 h4[8];
    const float4* hp = reinterpret_cast<const float4*>(&sH[tid * 36]);
#pragma unroll
    for (int i = 0; i < 8; i++) h4[i] = hp[i];

    const float4* w4 = reinterpret_cast<const float4*>(sW);
    float total = 0.0f;
#pragma unroll 4
    for (int o = 0; o < HID; o++) {
        float a0 = sb[o], a1 = 0.0f, a2 = 0.0f, a3 = 0.0f;
#pragma unroll
        for (int i = 0; i < 8; i++) {
            float4 w = w4[o * 8 + i];   // broadcast LDS.128
            a0 = fmaf(h4[i].x, w.x, a0);
            a1 = fmaf(h4[i].y, w.y, a1);
            a2 = fmaf(h4[i].z, w.z, a2);
            a3 = fmaf(h4[i].w, w.w, a3);
        }
        float acc = (a0 + a1) + (a2 + a3);
        total = fmaf(fmaxf(acc, 0.0f), sf2[o], total);
    }
    int n = base + tid;
    if (n < N_NODES) out[n] = total + fc2_b[0];
}

// ---------------------------------------------------------------------------
extern "C" void kernel_launch(void* const* d_in, const int* in_sizes, int n_in,
                              void* d_out, int out_size) {
    const float* x       = (const float*)d_in[0];
    const int*   ei      = (const int*)  d_in[1];
    const float* ea      = (const float*)d_in[2];
    const float* nn1_w   = (const float*)d_in[3];
    const float* nn1_b   = (const float*)d_in[4];
    const float* root1   = (const float*)d_in[5];
    const float* bias1   = (const float*)d_in[6];
    const float* nn2_w   = (const float*)d_in[7];
    const float* nn2_b   = (const float*)d_in[8];
    const float* root2   = (const float*)d_in[9];
    const float* bias2   = (const float*)d_in[10];
    const float* fc1_w   = (const float*)d_in[11];
    const float* fc1_b   = (const float*)d_in[12];
    const float* fc2_w   = (const float*)d_in[13];
    const float* fc2_b   = (const float*)d_in[14];
    float* out = (float*)d_out;

    const int tpb = 256;
    int gridEdge = (N_EDGES * 4 + tpb - 1) / tpb;         // 4688
    int gridK3   = (N_NODES + 127) / 128;                 // 782
    int gridK5   = (N_NODES + K5_NODES - 1) / K5_NODES;   // 391

    void* agg1_ptr = nullptr;
    cudaGetSymbolAddress(&agg1_ptr, g_agg1);
    cudaMemsetAsync(agg1_ptr, 0, sizeof(float) * N_NODES * HID, 0);

    k2_edges1<<<gridEdge, tpb>>>(ei, ea, nn1_w, nn1_b, x);
    k3_node2<<<gridK3, tpb>>>(x, root1, bias1, nn2_w, nn2_b, root2, bias2);
    k4_edges2<<<gridEdge, tpb>>>(ei, ea);
    k5_final<<<gridK5, tpb>>>(fc1_w, fc1_b, fc2_w, fc2_b, out);
}